// round 9
// baseline (speedup 1.0000x reference)
#include <cuda_runtime.h>

#define ADAM_B1 0.9f
#define ADAM_B2 0.999f
#define ADAM_LR 0.02f

// ---------------- packed f32x2 helpers ----------------
struct F2 { unsigned long long v; };

__device__ __forceinline__ F2 pk(float lo, float hi) {
    F2 r; asm("mov.b64 %0, {%1, %2};" : "=l"(r.v) : "f"(lo), "f"(hi)); return r;
}
__device__ __forceinline__ void upk(F2 a, float& lo, float& hi) {
    asm("mov.b64 {%0, %1}, %2;" : "=f"(lo), "=f"(hi) : "l"(a.v));
}
__device__ __forceinline__ F2 bc(float s) { return pk(s, s); }
__device__ __forceinline__ F2 fadd2(F2 a, F2 b) {
    F2 r; asm("add.rn.f32x2 %0, %1, %2;" : "=l"(r.v) : "l"(a.v), "l"(b.v)); return r;
}
__device__ __forceinline__ F2 fmul2(F2 a, F2 b) {
    F2 r; asm("mul.rn.f32x2 %0, %1, %2;" : "=l"(r.v) : "l"(a.v), "l"(b.v)); return r;
}
__device__ __forceinline__ F2 ffma2(F2 a, F2 b, F2 c) {
    F2 r; asm("fma.rn.f32x2 %0, %1, %2, %3;" : "=l"(r.v) : "l"(a.v), "l"(b.v), "l"(c.v)); return r;
}

__device__ __forceinline__ float rcp_a(float x) {
    float r; asm("rcp.approx.f32 %0, %1;" : "=f"(r) : "f"(x)); return r;
}
__device__ __forceinline__ float rsq_a(float x) {
    float r; asm("rsqrt.approx.f32 %0, %1;" : "=f"(r) : "f"(x)); return r;
}
__device__ __forceinline__ float sqrt_a(float x) {
    float r; asm("sqrt.approx.f32 %0, %1;" : "=f"(r) : "f"(x)); return r;
}
__device__ __forceinline__ float ex2_a(float x) {
    float r; asm("ex2.approx.f32 %0, %1;" : "=f"(r) : "f"(x)); return r;
}
__device__ __forceinline__ F2 frcp2(F2 a) {
    float lo, hi; upk(a, lo, hi); return pk(rcp_a(lo), rcp_a(hi));
}
__device__ __forceinline__ F2 frsq2(F2 a) {
    float lo, hi; upk(a, lo, hi); return pk(rsq_a(lo), rsq_a(hi));
}
#define EXPA(x) ex2_a(1.4426950408889634f * (x))

// ---------------- main kernel: 1 pixel per thread ----------------
// lambda pairs (0,1),(2,3) packed; lambda 4 scalar; Adam components (0,1) packed, 2 scalar.
__global__ __launch_bounds__(32, 22)   // force <=93 regs -> 22 blocks/SM -> single wave
void pe_kernel(const float* __restrict__ X,     // (B,5,5)
               const float* __restrict__ Yg,    // (B,5)
               const float* __restrict__ ch0g,  // (B,1,3)
               const float* __restrict__ pf,    // (14,)
               const float* __restrict__ xag,   // (3,)
               const float* __restrict__ Sag,   // (3,3)
               const float* __restrict__ Seg,   // (5,5)
               const int*   __restrict__ nitp,
               float* __restrict__ out,         // (B,9)
               int B)
{
    int b = blockIdx.x * blockDim.x + threadIdx.x;
    if (b >= B) return;

    const float L[5] = {-0.275f, 0.025f, 0.5f, 0.70f, 1.15f};

    // ---- uniform (broadcast) parameters ----
    float p0=pf[0], p1=pf[1], p2=pf[2], p3=pf[3], p4=pf[4], p5=pf[5], p6=pf[6],
          p7=pf[7], p8=pf[8], p9=pf[9], p10=pf[10], p11=pf[11], p12=pf[12], p13=pf[13];

    float AphS[5], AcdS[5], BbsS[5];
    #pragma unroll
    for (int l = 0; l < 5; l++) {
        AphS[l] = p0 * 0.05f * (1.0f + p1 * 0.1f * L[l] + p2 * 0.01f);
        AcdS[l] = p5 * 0.1f * expf(-p6 * 1.7f * L[l]);
        BbsS[l] = p3 * 0.001f * (1.0f + p4 * 0.05f * L[l]);
    }
    const float cna = p12 * 0.005f;
    const float cnb = p13 * 0.005f;
    const float c7s = p7 * 0.089f;
    const float c8s = p8 * 0.1245f;

    // symmetrized matrices (uniform)
    float Se[5][5];
    #pragma unroll
    for (int i = 0; i < 5; i++)
        #pragma unroll
        for (int j = 0; j < 5; j++)
            Se[i][j] = 0.5f * (Seg[i*5 + j] + Seg[j*5 + i]);
    float SaS[3][3];
    #pragma unroll
    for (int i = 0; i < 3; i++)
        #pragma unroll
        for (int j = 0; j < 3; j++)
            SaS[i][j] = 0.5f * (Sag[i*3 + j] + Sag[j*3 + i]);
    float xa0 = xag[0], xa1 = xag[1], xa2 = xag[2];

    bool diag = (Se[0][1]==0.f && Se[0][2]==0.f && Se[0][3]==0.f && Se[0][4]==0.f &&
                 Se[1][2]==0.f && Se[1][3]==0.f && Se[1][4]==0.f &&
                 Se[2][3]==0.f && Se[2][4]==0.f && Se[3][4]==0.f &&
                 SaS[0][1]==0.f && SaS[0][2]==0.f && SaS[1][2]==0.f);

    // ---- per-pixel setup ----
    float fe[5], yv[5];
    #pragma unroll
    for (int l = 0; l < 5; l++) {
        float e0 = X[b*25 + l*5 + 0], e1 = X[b*25 + l*5 + 1];
        fe[l] = __fdividef(e0 + 0.5f*e1, e0 + e1);
        yv[l] = Yg[b*5 + l];
    }

    float ch0v = ch0g[b*3 + 0];
    float ch1v = ch0g[b*3 + 1];
    float ch2v = ch0g[b*3 + 2];

    int iters = 50;
    if (nitp) {
        int it = *nitp;
        if (it >= 1 && it <= 100000000) iters = it;
        else {
            float f = __int_as_float(it);
            if (f >= 1.0f && f <= 1e8f) iters = (int)f;
        }
    }

    float b1t = 1.0f, b2t = 1.0f;

    if (diag) {
        // ===== fused diagonal path =====
        F2 ABSp[2], ABSn[2], ACDp[2], BBSp[2], FE2[2], YFN[2];
        #pragma unroll
        for (int i = 0; i < 2; i++) {
            int l0 = 2*i, l1 = 2*i + 1;
            float ab0 = AphS[l0] + BbsS[l0], ab1 = AphS[l1] + BbsS[l1];
            ABSp[i] = pk(ab0, ab1);
            ABSn[i] = pk(-ab0, -ab1);
            ACDp[i] = pk(AcdS[l0], AcdS[l1]);
            BBSp[i] = pk(BbsS[l0], BbsS[l1]);
            FE2[i]  = pk(Se[l0][l0]*fe[l0]*fe[l0], Se[l1][l1]*fe[l1]*fe[l1]);
            YFN[i]  = pk(-__fdividef(yv[l0], fe[l0]), -__fdividef(yv[l1], fe[l1]));
        }
        // scalar lambda-4 constants
        const float ab4 = AphS[4] + BbsS[4];
        const float acd4 = AcdS[4], bbs4 = BbsS[4];
        const float fe24 = Se[4][4]*fe[4]*fe[4];
        const float yfn4 = -__fdividef(yv[4], fe[4]);

        const float sa2 = SaS[2][2];
        const float bp2 = -sa2*xa2;
        const float cnab = cna + cnb;
        const F2 C7p = bc(c7s), C8p = bc(c8s);
        const F2 SA01 = pk(SaS[0][0], SaS[1][1]);
        const F2 BP01 = pk(-SaS[0][0]*xa0, -SaS[1][1]*xa1);
        const F2 CB1p = bc(ADAM_B1), C1MB1p = bc(1.0f - ADAM_B1);
        const F2 CB2p = bc(ADAM_B2), C1MB2p = bc(1.0f - ADAM_B2);
        const F2 ONEp = bc(1.0f), HALFp = bc(0.5f), C6Ip = bc(1.0f/6.0f);

        // Adam state: components (0,1) packed, 2 scalar
        F2 ch01 = pk(ch0v, ch1v);
        F2 m01 = bc(0.0f), v01 = bc(1e-30f);
        float m2 = 0.0f, v2 = 1e-30f;

        // tracked exponentials: ex01 = (chla, nap) packed, cdom scalar
        F2 ex01 = pk(EXPA(ch0v), EXPA(ch1v));
        float excd = EXPA(ch2v);

        for (int t = 0; t < iters; t++) {
            float chla, nap;
            upk(ex01, chla, nap);       // register aliases
            float cdom = excd;

            float dbb1  = cnb * nap;
            float dsum1 = cnab * nap;
            float NCs   = dsum1 + 0.0057f;
            float DB1Cs = dbb1 + 0.0012f;

            F2 CHLA2 = bc(chla), CDOM2 = bc(cdom);
            F2 NC2 = bc(NCs), DB1C2 = bc(DB1Cs);

            F2 acc0p = bc(0.0f), S0p = bc(0.0f), S1p = bc(0.0f), acc2p = bc(0.0f);

            #pragma unroll
            for (int i = 0; i < 2; i++) {
                F2 s  = ffma2(ABSp[i], CHLA2, ffma2(ACDp[i], CDOM2, NC2)); // a+bb
                F2 bb = ffma2(BBSp[i], CHLA2, DB1C2);
                F2 iv = frcp2(s);
                F2 u  = fmul2(bb, iv);
                F2 t1 = ffma2(C8p, u, C7p);
                F2 p  = ffma2(t1, u, YFN[i]);        // rrs/FE - Y/FE
                F2 d  = ffma2(C8p, u, t1);           // c7 + 2 c8 u
                F2 q  = fmul2(fmul2(FE2[i], iv), fmul2(p, d));
                F2 qu = fmul2(q, u);
                F2 tg = ffma2(u, ABSn[i], BBSp[i]);  // BBS - u*(Aph+Bbs)
                acc0p = ffma2(q, tg, acc0p);
                S0p   = fadd2(S0p, q);
                S1p   = fadd2(S1p, qu);
                acc2p = ffma2(qu, ACDp[i], acc2p);
            }

            // scalar lambda 4
            float s4  = fmaf(ab4, chla, fmaf(acd4, cdom, NCs));
            float bb4 = fmaf(bbs4, chla, DB1Cs);
            float iv4 = rcp_a(s4);
            float u4  = bb4 * iv4;
            float t14 = fmaf(c8s, u4, c7s);
            float p4v = fmaf(t14, u4, yfn4);
            float d4  = fmaf(c8s, u4, t14);
            float q4  = (fe24 * iv4) * (p4v * d4);
            float qu4 = q4 * u4;
            float tg4 = fmaf(-u4, ab4, bbs4);

            // lane reduction
            float a0l, a0h, s0l, s0h, s1l, s1h, a2l, a2h;
            upk(acc0p, a0l, a0h); upk(S0p, s0l, s0h);
            upk(S1p, s1l, s1h);   upk(acc2p, a2l, a2h);
            float acc0 = fmaf(q4, tg4, a0l + a0h);
            float S0   = (s0l + s0h) + q4;
            float S1   = (s1l + s1h) + qu4;
            float acc2 = fmaf(qu4, acd4, a2l + a2h);

            // gradients: g0, g1 packed; g2 scalar
            float gd0 = acc0 * chla;
            float gd1 = fmaf(dbb1, S0, -dsum1 * S1);
            F2 g01 = fadd2(pk(gd0, gd1), ffma2(SA01, ch01, BP01));
            float g2 = fmaf(-acc2, cdom, fmaf(sa2, ch2v, bp2));

            // scalar step size with exact bias correction
            b1t *= ADAM_B1; b2t *= ADAM_B2;
            float nlrt = -ADAM_LR * sqrt_a(1.0f - b2t) * rcp_a(1.0f - b1t);
            F2 NLRT2 = bc(nlrt);

            // Adam packed (0,1)
            m01 = ffma2(g01, C1MB1p, fmul2(m01, CB1p));
            v01 = ffma2(fmul2(g01, g01), C1MB2p, fmul2(v01, CB2p));
            F2 dlt01 = fmul2(fmul2(m01, frsq2(v01)), NLRT2);
            ch01 = fadd2(ch01, dlt01);
            // packed e^dlt poly (deg-3)
            F2 h01 = ffma2(dlt01, C6Ip, HALFp);
            h01 = ffma2(dlt01, h01, ONEp);
            h01 = ffma2(dlt01, h01, ONEp);
            ex01 = fmul2(ex01, h01);

            // Adam scalar (2)
            m2 = fmaf(g2, 1.0f - ADAM_B1, m2 * ADAM_B1);
            v2 = fmaf(g2 * g2, 1.0f - ADAM_B2, v2 * ADAM_B2);
            float dlt2 = nlrt * m2 * rsq_a(v2);
            ch2v += dlt2;
            float h2 = fmaf(dlt2, 1.0f/6.0f, 0.5f);
            h2 = fmaf(dlt2, h2, 1.0f);
            h2 = fmaf(dlt2, h2, 1.0f);
            excd *= h2;
        }
        upk(ch01, ch0v, ch1v);
    } else {
        // ===== general scalar two-pass fallback (dense Se, Sa) =====
        float ch[3] = { ch0v, ch1v, ch2v };
        float m[3] = {0.f,0.f,0.f}, v[3] = {1e-30f,1e-30f,1e-30f};
        float bp0 = -(SaS[0][0]*xa0 + SaS[0][1]*xa1 + SaS[0][2]*xa2);
        float bp1 = -(SaS[1][0]*xa0 + SaS[1][1]*xa1 + SaS[1][2]*xa2);
        float bp2 = -(SaS[2][0]*xa0 + SaS[2][1]*xa1 + SaS[2][2]*xa2);

        for (int t = 0; t < iters; t++) {
            float chla = EXPA(ch[0]);
            float nap  = EXPA(ch[1]);
            float cdom = EXPA(ch[2]);

            float da1  = cna * nap;
            float dbb1 = cnb * nap;

            float r[5], u[5], iv[5];
            #pragma unroll
            for (int l = 0; l < 5; l++) {
                float a  = 0.0045f + AphS[l]*chla + AcdS[l]*cdom + da1;
                float bb = 0.0012f + BbsS[l]*chla + dbb1;
                iv[l] = rcp_a(a + bb);
                u[l]  = bb * iv[l];
                float rrs = fmaf(c8s, u[l], c7s) * u[l] * fe[l];
                r[l] = rrs - yv[l];
            }

            float g0 = fmaf(SaS[0][0], ch[0], fmaf(SaS[0][1], ch[1], fmaf(SaS[0][2], ch[2], bp0)));
            float g1 = fmaf(SaS[1][0], ch[0], fmaf(SaS[1][1], ch[1], fmaf(SaS[1][2], ch[2], bp1)));
            float g2 = fmaf(SaS[2][0], ch[0], fmaf(SaS[2][1], ch[1], fmaf(SaS[2][2], ch[2], bp2)));

            #pragma unroll
            for (int l = 0; l < 5; l++) {
                float w = fmaf(Se[l][0], r[0], fmaf(Se[l][1], r[1],
                          fmaf(Se[l][2], r[2], fmaf(Se[l][3], r[3], Se[l][4]*r[4]))));
                float dg = fmaf(2.0f*c8s, u[l], c7s) * fe[l];
                float q  = w * dg * iv[l];
                float ul = u[l], om = 1.0f - ul;
                float da0 = AphS[l]*chla, dbb0 = BbsS[l]*chla;
                float da2 = AcdS[l]*cdom;
                g0 += q * (om * dbb0 - ul * da0);
                g1 += q * (om * dbb1 - ul * da1);
                g2 -= q * ul * da2;
            }

            b1t *= ADAM_B1; b2t *= ADAM_B2;
            float nlrt = -ADAM_LR * sqrt_a(1.0f - b2t) * rcp_a(1.0f - b1t);
            float g[3] = { g0, g1, g2 };
            #pragma unroll
            for (int k = 0; k < 3; k++) {
                m[k] = fmaf(g[k], 1.0f - ADAM_B1, m[k] * ADAM_B1);
                v[k] = fmaf(g[k] * g[k], 1.0f - ADAM_B2, v[k] * ADAM_B2);
                ch[k] += nlrt * m[k] * rsq_a(v[k]);
            }
        }
        ch0v = ch[0]; ch1v = ch[1]; ch2v = ch[2];
    }

    // ---- outputs: [ch0, kd(5), bbp(3)] ----
    float kfac = p9 * 0.9f + p10 * 0.1f;
    float chla = EXPA(ch0v);
    float nap  = EXPA(ch1v);
    float cdom = EXPA(ch2v);

    out[b*9 + 0] = ch0v;
    #pragma unroll
    for (int l = 0; l < 5; l++) {
        float a  = 0.0045f + AphS[l]*chla + AcdS[l]*cdom + cna*nap;
        float bb = 0.0012f + BbsS[l]*chla + cnb*nap;
        float x3 = X[b*25 + l*5 + 3];
        float mu = 0.5f + 0.5f * rcp_a(1.0f + EXPA(-x3));
        out[b*9 + 1 + l] = (a + bb) * rcp_a(mu) * kfac;
    }
    const float L3[3] = {0.025f, 0.5f, 1.15f};
    #pragma unroll
    for (int j = 0; j < 3; j++) {
        out[b*9 + 6 + j] = p11 * (p3 * 0.001f * chla * (1.0f + p4 * 0.05f * L3[j]) + cnb * nap);
    }
}

extern "C" void kernel_launch(void* const* d_in, const int* in_sizes, int n_in,
                              void* d_out, int out_size) {
    const float* X    = (const float*)d_in[0];
    const float* Y    = (const float*)d_in[1];
    const float* ch0  = (const float*)d_in[2];
    const float* pf   = (const float*)d_in[3];
    const float* xa   = (const float*)d_in[4];
    const float* Sa   = (const float*)d_in[5];
    const float* Se   = (const float*)d_in[6];
    const int*   nit  = (n_in >= 8) ? (const int*)d_in[7] : nullptr;
    float* out = (float*)d_out;

    int B = in_sizes[1] / 5;   // Y is (B,5)

    const int TPB = 32;
    int blocks = (B + TPB - 1) / TPB;
    pe_kernel<<<blocks, TPB>>>(X, Y, ch0, pf, xa, Sa, Se, nit, out, B);
}

// round 10
// speedup vs baseline: 1.0031x; 1.0031x over previous
#include <cuda_runtime.h>

#define ADAM_B1 0.9f
#define ADAM_B2 0.999f
#define ADAM_LR 0.02f

// ---------------- packed f32x2 helpers ----------------
struct F2 { unsigned long long v; };

__device__ __forceinline__ F2 pk(float lo, float hi) {
    F2 r; asm("mov.b64 %0, {%1, %2};" : "=l"(r.v) : "f"(lo), "f"(hi)); return r;
}
__device__ __forceinline__ void upk(F2 a, float& lo, float& hi) {
    asm("mov.b64 {%0, %1}, %2;" : "=f"(lo), "=f"(hi) : "l"(a.v));
}
__device__ __forceinline__ F2 bc(float s) { return pk(s, s); }
__device__ __forceinline__ F2 fadd2(F2 a, F2 b) {
    F2 r; asm("add.rn.f32x2 %0, %1, %2;" : "=l"(r.v) : "l"(a.v), "l"(b.v)); return r;
}
__device__ __forceinline__ F2 fmul2(F2 a, F2 b) {
    F2 r; asm("mul.rn.f32x2 %0, %1, %2;" : "=l"(r.v) : "l"(a.v), "l"(b.v)); return r;
}
__device__ __forceinline__ F2 ffma2(F2 a, F2 b, F2 c) {
    F2 r; asm("fma.rn.f32x2 %0, %1, %2, %3;" : "=l"(r.v) : "l"(a.v), "l"(b.v), "l"(c.v)); return r;
}

__device__ __forceinline__ float rcp_a(float x) {
    float r; asm("rcp.approx.f32 %0, %1;" : "=f"(r) : "f"(x)); return r;
}
__device__ __forceinline__ float rsq_a(float x) {
    float r; asm("rsqrt.approx.f32 %0, %1;" : "=f"(r) : "f"(x)); return r;
}
__device__ __forceinline__ float sqrt_a(float x) {
    float r; asm("sqrt.approx.f32 %0, %1;" : "=f"(r) : "f"(x)); return r;
}
__device__ __forceinline__ float ex2_a(float x) {
    float r; asm("ex2.approx.f32 %0, %1;" : "=f"(r) : "f"(x)); return r;
}
__device__ __forceinline__ F2 frcp2(F2 a) {
    float lo, hi; upk(a, lo, hi); return pk(rcp_a(lo), rcp_a(hi));
}
__device__ __forceinline__ F2 frsq2(F2 a) {
    float lo, hi; upk(a, lo, hi); return pk(rsq_a(lo), rsq_a(hi));
}
__device__ __forceinline__ F2 fexp2(F2 a) {
    F2 t = fmul2(a, bc(1.4426950408889634f));
    float lo, hi; upk(t, lo, hi);
    return pk(ex2_a(lo), ex2_a(hi));
}
#define EXPA(x) ex2_a(1.4426950408889634f * (x))

// ---------------- main kernel: 2 pixels per thread, packed across pixels ----------------
__global__ __launch_bounds__(32)
void pe_kernel(const float* __restrict__ X,     // (B,5,5)
               const float* __restrict__ Yg,    // (B,5)
               const float* __restrict__ ch0g,  // (B,1,3)
               const float* __restrict__ pf,    // (14,)
               const float* __restrict__ xag,   // (3,)
               const float* __restrict__ Sag,   // (3,3)
               const float* __restrict__ Seg,   // (5,5)
               const int*   __restrict__ nitp,
               float* __restrict__ out,         // (B,9)
               int B)
{
    int tIdx = blockIdx.x * blockDim.x + threadIdx.x;
    int pA = 2 * tIdx;
    if (pA >= B) return;
    int pB = min(pA + 1, B - 1);

    const float L[5] = {-0.275f, 0.025f, 0.5f, 0.70f, 1.15f};

    F2 ch[3], m[3], v[3];
    float b1t = 1.0f, b2t = 1.0f;

    int iters = 50;
    if (nitp) {
        int it = *nitp;
        if (it >= 1 && it <= 100000000) iters = it;
        else {
            float f = __int_as_float(it);
            if (f >= 1.0f && f <= 1e8f) iters = (int)f;
        }
    }

    bool diag;

    // ====================== setup scope (locals die before main loop) ======================
    {
        float p0=pf[0], p1=pf[1], p2=pf[2], p3=pf[3], p4=pf[4], p5=pf[5], p6=pf[6],
              p12=pf[12], p13=pf[13];

        float SeD[5];          // diagonal of symmetrized Se
        {
            // symmetrization: diagonal entries are unchanged
            #pragma unroll
            for (int i = 0; i < 5; i++) SeD[i] = Seg[i*5 + i];
        }
        // off-diagonal zero checks (symmetrized off-diag zero iff Se[i][j]+Se[j][i]==0)
        diag = ((Seg[0*5+1]+Seg[1*5+0])==0.f && (Seg[0*5+2]+Seg[2*5+0])==0.f &&
                (Seg[0*5+3]+Seg[3*5+0])==0.f && (Seg[0*5+4]+Seg[4*5+0])==0.f &&
                (Seg[1*5+2]+Seg[2*5+1])==0.f && (Seg[1*5+3]+Seg[3*5+1])==0.f &&
                (Seg[1*5+4]+Seg[4*5+1])==0.f && (Seg[2*5+3]+Seg[3*5+2])==0.f &&
                (Seg[2*5+4]+Seg[4*5+2])==0.f && (Seg[3*5+4]+Seg[4*5+3])==0.f &&
                (Sag[0*3+1]+Sag[1*3+0])==0.f && (Sag[0*3+2]+Sag[2*3+0])==0.f &&
                (Sag[1*3+2]+Sag[2*3+1])==0.f);

        #pragma unroll
        for (int k = 0; k < 3; k++) {
            ch[k] = pk(ch0g[pA*3 + k], ch0g[pB*3 + k]);
            m[k] = bc(0.0f);
            v[k] = bc(1e-30f);   // exact-effect-free floor: keeps rsqrt finite
        }

        if (diag) {
            const float cna = p12 * 0.005f;
            const float cnb = p13 * 0.005f;
            const float c7s = pf[7] * 0.089f;
            const float c8s = pf[8] * 0.1245f;

            // per-lambda broadcast constants
            F2 ABSp[5], ACDp[5], BBSp[5], FE2[5], YFN[5];
            #pragma unroll
            for (int l = 0; l < 5; l++) {
                float aph = p0 * 0.05f * (1.0f + p1 * 0.1f * L[l] + p2 * 0.01f);
                float acd = p5 * 0.1f * EXPA(-p6 * 1.7f * L[l]);
                float bbs = p3 * 0.001f * (1.0f + p4 * 0.05f * L[l]);
                ABSp[l] = bc(aph + bbs);
                ACDp[l] = bc(acd);
                BBSp[l] = bc(bbs);
                float eA0 = X[pA*25 + l*5 + 0], eA1 = X[pA*25 + l*5 + 1];
                float eB0 = X[pB*25 + l*5 + 0], eB1 = X[pB*25 + l*5 + 1];
                float feA = __fdividef(eA0 + 0.5f*eA1, eA0 + eA1);
                float feB = __fdividef(eB0 + 0.5f*eB1, eB0 + eB1);
                FE2[l] = pk(SeD[l]*feA*feA, SeD[l]*feB*feB);
                YFN[l] = pk(-__fdividef(Yg[pA*5 + l], feA),
                            -__fdividef(Yg[pB*5 + l], feB));
            }
            const F2 SAD[3] = { bc(Sag[0]), bc(Sag[4]), bc(Sag[8]) };
            const F2 BPD[3] = { bc(-Sag[0]*xag[0]), bc(-Sag[4]*xag[1]), bc(-Sag[8]*xag[2]) };
            const F2 CNAB = bc(cna + cnb), CNBp = bc(cnb);
            const F2 C7p = bc(c7s), C8p = bc(c8s);
            const F2 C0057 = bc(0.0057f), C0012 = bc(0.0012f);
            const F2 NEG1 = bc(-1.0f), ONEp = bc(1.0f), HALFp = bc(0.5f), C6Ip = bc(1.0f/6.0f);
            const F2 CB1p = bc(ADAM_B1), C1MB1p = bc(1.0f - ADAM_B1);
            const F2 CB2p = bc(ADAM_B2), C1MB2p = bc(1.0f - ADAM_B2);

            // tracked exponentials
            F2 ex0 = fexp2(ch[0]);   // chla
            F2 ex1 = fexp2(ch[1]);   // nap
            F2 ex2v = fexp2(ch[2]);  // cdom

            for (int t = 0; t < iters; t++) {
                // step size (uniform scalar; off the gradient critical path)
                b1t *= ADAM_B1; b2t *= ADAM_B2;
                float nlrt = -ADAM_LR * sqrt_a(1.0f - b2t) * rcp_a(1.0f - b1t);
                F2 NLRT2 = bc(nlrt);

                F2 chla = ex0, nap = ex1, cdom = ex2v;

                F2 dbb1   = fmul2(CNBp, nap);
                F2 dsum1  = fmul2(CNAB, nap);
                F2 dsum1n = fmul2(dsum1, NEG1);
                F2 NC     = fadd2(dsum1, C0057);
                F2 DB1C   = fadd2(dbb1, C0012);

                // even/odd split accumulators
                F2 a0e = bc(0.0f), a0o = bc(0.0f);
                F2 s0e = bc(0.0f), s0o = bc(0.0f);
                F2 s1e = bc(0.0f), s1o = bc(0.0f);
                F2 a2e = bc(0.0f), a2o = bc(0.0f);

                #pragma unroll
                for (int l = 0; l < 5; l++) {
                    F2 s  = ffma2(ABSp[l], chla, ffma2(ACDp[l], cdom, NC)); // a+bb
                    F2 bb = ffma2(BBSp[l], chla, DB1C);
                    F2 iv = frcp2(s);
                    F2 u  = fmul2(bb, iv);
                    F2 t1 = ffma2(C8p, u, C7p);
                    F2 p  = ffma2(t1, u, YFN[l]);        // rrs/FE - Y/FE
                    F2 d  = ffma2(C8p, u, t1);           // c7 + 2 c8 u
                    F2 q  = fmul2(fmul2(FE2[l], iv), fmul2(p, d));
                    F2 qu = fmul2(q, u);
                    F2 un = fmul2(u, NEG1);
                    F2 tg = ffma2(un, ABSp[l], BBSp[l]); // BBS - u*(Aph+Bbs)
                    if (l & 1) {
                        a0o = ffma2(q, tg, a0o);
                        s0o = fadd2(s0o, q);
                        s1o = fadd2(s1o, qu);
                        a2o = ffma2(qu, ACDp[l], a2o);
                    } else {
                        a0e = ffma2(q, tg, a0e);
                        s0e = fadd2(s0e, q);
                        s1e = fadd2(s1e, qu);
                        a2e = ffma2(qu, ACDp[l], a2e);
                    }
                }
                F2 acc0 = fadd2(a0e, a0o);
                F2 S0   = fadd2(s0e, s0o);
                F2 S1   = fadd2(s1e, s1o);
                F2 acc2 = fadd2(a2e, a2o);

                // gradients
                F2 g0 = ffma2(acc0, chla, ffma2(SAD[0], ch[0], BPD[0]));
                F2 g1 = ffma2(SAD[1], ch[1], BPD[1]);
                g1 = ffma2(dbb1, S0, g1);
                g1 = ffma2(dsum1n, S1, g1);
                F2 g2t = fmul2(acc2, cdom);
                F2 g2 = ffma2(g2t, NEG1, ffma2(SAD[2], ch[2], BPD[2]));

                F2 g[3] = { g0, g1, g2 };
                F2* exs[3] = { &ex0, &ex1, &ex2v };
                #pragma unroll
                for (int k = 0; k < 3; k++) {
                    m[k] = ffma2(g[k], C1MB1p, fmul2(m[k], CB1p));
                    v[k] = ffma2(fmul2(g[k], g[k]), C1MB2p, fmul2(v[k], CB2p));
                    F2 st  = frsq2(v[k]);
                    F2 dlt = fmul2(fmul2(m[k], st), NLRT2);
                    ch[k] = fadd2(ch[k], dlt);
                    // e^dlt via degree-3 poly (|dlt| <= ~0.06)
                    F2 h = ffma2(dlt, C6Ip, HALFp);
                    h = ffma2(dlt, h, ONEp);
                    h = ffma2(dlt, h, ONEp);
                    *exs[k] = fmul2(*exs[k], h);
                }
            }
        } else {
            // ===== general two-pass fallback (dense Se, Sa) — packed 2px =====
            float Se[5][5];
            #pragma unroll
            for (int i = 0; i < 5; i++)
                #pragma unroll
                for (int j = 0; j < 5; j++)
                    Se[i][j] = 0.5f * (Seg[i*5 + j] + Seg[j*5 + i]);
            float SaS[3][3];
            #pragma unroll
            for (int i = 0; i < 3; i++)
                #pragma unroll
                for (int j = 0; j < 3; j++)
                    SaS[i][j] = 0.5f * (Sag[i*3 + j] + Sag[j*3 + i]);
            float xa0 = xag[0], xa1 = xag[1], xa2 = xag[2];

            const float cna = p12 * 0.005f;
            const float cnb = p13 * 0.005f;
            const float c7s = pf[7] * 0.089f;
            const float c8s = pf[8] * 0.1245f;

            float AphS[5], AcdS[5], BbsS[5];
            #pragma unroll
            for (int l = 0; l < 5; l++) {
                AphS[l] = p0 * 0.05f * (1.0f + p1 * 0.1f * L[l] + p2 * 0.01f);
                AcdS[l] = p5 * 0.1f * EXPA(-p6 * 1.7f * L[l]);
                BbsS[l] = p3 * 0.001f * (1.0f + p4 * 0.05f * L[l]);
            }

            const F2 CNA = bc(cna), CNBp = bc(cnb);
            const F2 C7p = bc(c7s), C8p = bc(c8s), C82 = bc(2.0f*c8s);
            const F2 C0045 = bc(0.0045f), C0012 = bc(0.0012f);
            const F2 NEG1 = bc(-1.0f), ONEg = bc(1.0f);
            const F2 CB1p = bc(ADAM_B1), C1MB1p = bc(1.0f - ADAM_B1);
            const F2 CB2p = bc(ADAM_B2), C1MB2p = bc(1.0f - ADAM_B2);
            const F2 APH[5] = { bc(AphS[0]), bc(AphS[1]), bc(AphS[2]), bc(AphS[3]), bc(AphS[4]) };
            const F2 ACD[5] = { bc(AcdS[0]), bc(AcdS[1]), bc(AcdS[2]), bc(AcdS[3]), bc(AcdS[4]) };
            const F2 BBS[5] = { bc(BbsS[0]), bc(BbsS[1]), bc(BbsS[2]), bc(BbsS[3]), bc(BbsS[4]) };
            F2 FE[5], Yp[5];
            #pragma unroll
            for (int l = 0; l < 5; l++) {
                float eA0 = X[pA*25 + l*5 + 0], eA1 = X[pA*25 + l*5 + 1];
                float eB0 = X[pB*25 + l*5 + 0], eB1 = X[pB*25 + l*5 + 1];
                FE[l] = pk(__fdividef(eA0 + 0.5f*eA1, eA0 + eA1),
                           __fdividef(eB0 + 0.5f*eB1, eB0 + eB1));
                Yp[l] = pk(-Yg[pA*5 + l], -Yg[pB*5 + l]);
            }
            float bp0 = -(SaS[0][0]*xa0 + SaS[0][1]*xa1 + SaS[0][2]*xa2);
            float bp1 = -(SaS[1][0]*xa0 + SaS[1][1]*xa1 + SaS[1][2]*xa2);
            float bp2 = -(SaS[2][0]*xa0 + SaS[2][1]*xa1 + SaS[2][2]*xa2);

            for (int t = 0; t < iters; t++) {
                F2 chla = fexp2(ch[0]);
                F2 nap  = fexp2(ch[1]);
                F2 cdom = fexp2(ch[2]);

                F2 da1  = fmul2(CNA, nap);
                F2 dbb1 = fmul2(CNBp, nap);

                F2 u[5], iv[5];
                float rA[5], rB[5];
                #pragma unroll
                for (int l = 0; l < 5; l++) {
                    F2 da0  = fmul2(APH[l], chla);
                    F2 da2  = fmul2(ACD[l], cdom);
                    F2 dbb0 = fmul2(BBS[l], chla);
                    F2 a  = fadd2(fadd2(da0, da2), fadd2(da1, C0045));
                    F2 bb = fadd2(dbb0, fadd2(dbb1, C0012));
                    F2 ivv = frcp2(fadd2(a, bb));
                    F2 uv  = fmul2(bb, ivv);
                    F2 rrs = fmul2(fmul2(ffma2(C8p, uv, C7p), uv), FE[l]);
                    F2 rr  = fadd2(rrs, Yp[l]);
                    upk(rr, rA[l], rB[l]);
                    u[l] = uv; iv[l] = ivv;
                }

                float cA0, cB0, cA1, cB1, cA2, cB2;
                upk(ch[0], cA0, cB0); upk(ch[1], cA1, cB1); upk(ch[2], cA2, cB2);
                float gA0 = fmaf(SaS[0][0], cA0, fmaf(SaS[0][1], cA1, fmaf(SaS[0][2], cA2, bp0)));
                float gB0 = fmaf(SaS[0][0], cB0, fmaf(SaS[0][1], cB1, fmaf(SaS[0][2], cB2, bp0)));
                float gA1 = fmaf(SaS[1][0], cA0, fmaf(SaS[1][1], cA1, fmaf(SaS[1][2], cA2, bp1)));
                float gB1 = fmaf(SaS[1][0], cB0, fmaf(SaS[1][1], cB1, fmaf(SaS[1][2], cB2, bp1)));
                float gA2 = fmaf(SaS[2][0], cA0, fmaf(SaS[2][1], cA1, fmaf(SaS[2][2], cA2, bp2)));
                float gB2 = fmaf(SaS[2][0], cB0, fmaf(SaS[2][1], cB1, fmaf(SaS[2][2], cB2, bp2)));
                F2 g0 = pk(gA0, gB0);
                F2 g1 = pk(gA1, gB1);
                F2 g2 = pk(gA2, gB2);

                #pragma unroll
                for (int l = 0; l < 5; l++) {
                    float wA = fmaf(Se[l][4], rA[4],
                               fmaf(Se[l][0], rA[0], Se[l][1]*rA[1]) +
                               fmaf(Se[l][2], rA[2], Se[l][3]*rA[3]));
                    float wB = fmaf(Se[l][4], rB[4],
                               fmaf(Se[l][0], rB[0], Se[l][1]*rB[1]) +
                               fmaf(Se[l][2], rB[2], Se[l][3]*rB[3]));
                    F2 w  = pk(wA, wB);
                    F2 dg = fmul2(ffma2(C82, u[l], C7p), FE[l]);
                    F2 q  = fmul2(fmul2(w, dg), iv[l]);

                    F2 da0  = fmul2(APH[l], chla);
                    F2 dbb0 = fmul2(BBS[l], chla);
                    F2 da2  = fmul2(ACD[l], cdom);
                    F2 om   = ffma2(u[l], NEG1, ONEg);

                    F2 x0 = ffma2(fmul2(u[l], da0), NEG1, fmul2(om, dbb0));
                    F2 x1 = ffma2(fmul2(u[l], da1), NEG1, fmul2(om, dbb1));
                    F2 qun = fmul2(fmul2(q, u[l]), NEG1);
                    g0 = ffma2(q, x0, g0);
                    g1 = ffma2(q, x1, g1);
                    g2 = ffma2(qun, da2, g2);
                }

                b1t *= ADAM_B1; b2t *= ADAM_B2;
                float nlrt = -ADAM_LR * sqrt_a(1.0f - b2t) * rcp_a(1.0f - b1t);
                F2 NLRT2 = bc(nlrt);
                F2 g[3] = { g0, g1, g2 };
                #pragma unroll
                for (int k = 0; k < 3; k++) {
                    m[k] = ffma2(g[k], C1MB1p, fmul2(m[k], CB1p));
                    v[k] = ffma2(fmul2(g[k], g[k]), C1MB2p, fmul2(v[k], CB2p));
                    F2 st = frsq2(v[k]);
                    ch[k] = ffma2(fmul2(m[k], st), NLRT2, ch[k]);
                }
            }
        }
    } // setup/loop scope ends

    // ====================== epilogue: recompute uniform constants ======================
    {
        float q0=pf[0], q1=pf[1], q2=pf[2], q3=pf[3], q4=pf[4], q5=pf[5], q6=pf[6],
              q9=pf[9], q10=pf[10], q11=pf[11], q12=pf[12], q13=pf[13];
        float Aph[5], Acd[5], Bbs[5];
        #pragma unroll
        for (int l = 0; l < 5; l++) {
            Aph[l] = q0 * 0.05f * (1.0f + q1 * 0.1f * L[l] + q2 * 0.01f);
            Acd[l] = q5 * 0.1f * EXPA(-q6 * 1.7f * L[l]);
            Bbs[l] = q3 * 0.001f * (1.0f + q4 * 0.05f * L[l]);
        }
        float cna = q12 * 0.005f, cnb = q13 * 0.005f;
        float kfac = q9 * 0.9f + q10 * 0.1f;

        float chL[3], chH[3];
        #pragma unroll
        for (int k = 0; k < 3; k++) upk(ch[k], chL[k], chH[k]);

        #pragma unroll
        for (int s = 0; s < 2; s++) {
            int b = s ? pB : pA;
            const float* chp = s ? chH : chL;
            float chla = EXPA(chp[0]);
            float nap  = EXPA(chp[1]);
            float cdom = EXPA(chp[2]);

            out[b*9 + 0] = chp[0];
            #pragma unroll
            for (int l = 0; l < 5; l++) {
                float a  = 0.0045f + Aph[l]*chla + Acd[l]*cdom + cna*nap;
                float bb = 0.0012f + Bbs[l]*chla + cnb*nap;
                float x3 = X[b*25 + l*5 + 3];
                float mu = 0.5f + 0.5f * rcp_a(1.0f + EXPA(-x3));
                out[b*9 + 1 + l] = (a + bb) * rcp_a(mu) * kfac;
            }
            const float L3[3] = {0.025f, 0.5f, 1.15f};
            #pragma unroll
            for (int j = 0; j < 3; j++) {
                out[b*9 + 6 + j] = q11 * (q3 * 0.001f * chla * (1.0f + q4 * 0.05f * L3[j]) + cnb * nap);
            }
        }
    }
}

extern "C" void kernel_launch(void* const* d_in, const int* in_sizes, int n_in,
                              void* d_out, int out_size) {
    const float* X    = (const float*)d_in[0];
    const float* Y    = (const float*)d_in[1];
    const float* ch0  = (const float*)d_in[2];
    const float* pf   = (const float*)d_in[3];
    const float* xa   = (const float*)d_in[4];
    const float* Sa   = (const float*)d_in[5];
    const float* Se   = (const float*)d_in[6];
    const int*   nit  = (n_in >= 8) ? (const int*)d_in[7] : nullptr;
    float* out = (float*)d_out;

    int B = in_sizes[1] / 5;   // Y is (B,5)
    int nThreads = (B + 1) / 2;

    const int TPB = 32;
    int blocks = (nThreads + TPB - 1) / TPB;
    pe_kernel<<<blocks, TPB>>>(X, Y, ch0, pf, xa, Sa, Se, nit, out, B);
}

// round 11
// speedup vs baseline: 1.0452x; 1.0420x over previous
#include <cuda_runtime.h>

#define ADAM_B1 0.9f
#define ADAM_B2 0.999f
#define ADAM_LR 0.02f

// ---------------- packed f32x2 helpers ----------------
struct F2 { unsigned long long v; };

__device__ __forceinline__ F2 pk(float lo, float hi) {
    F2 r; asm("mov.b64 %0, {%1, %2};" : "=l"(r.v) : "f"(lo), "f"(hi)); return r;
}
__device__ __forceinline__ void upk(F2 a, float& lo, float& hi) {
    asm("mov.b64 {%0, %1}, %2;" : "=f"(lo), "=f"(hi) : "l"(a.v));
}
__device__ __forceinline__ F2 bc(float s) { return pk(s, s); }
__device__ __forceinline__ F2 fadd2(F2 a, F2 b) {
    F2 r; asm("add.rn.f32x2 %0, %1, %2;" : "=l"(r.v) : "l"(a.v), "l"(b.v)); return r;
}
__device__ __forceinline__ F2 fmul2(F2 a, F2 b) {
    F2 r; asm("mul.rn.f32x2 %0, %1, %2;" : "=l"(r.v) : "l"(a.v), "l"(b.v)); return r;
}
__device__ __forceinline__ F2 ffma2(F2 a, F2 b, F2 c) {
    F2 r; asm("fma.rn.f32x2 %0, %1, %2, %3;" : "=l"(r.v) : "l"(a.v), "l"(b.v), "l"(c.v)); return r;
}

__device__ __forceinline__ float rcp_a(float x) {
    float r; asm("rcp.approx.f32 %0, %1;" : "=f"(r) : "f"(x)); return r;
}
__device__ __forceinline__ float rsq_a(float x) {
    float r; asm("rsqrt.approx.f32 %0, %1;" : "=f"(r) : "f"(x)); return r;
}
__device__ __forceinline__ float sqrt_a(float x) {
    float r; asm("sqrt.approx.f32 %0, %1;" : "=f"(r) : "f"(x)); return r;
}
__device__ __forceinline__ float ex2_a(float x) {
    float r; asm("ex2.approx.f32 %0, %1;" : "=f"(r) : "f"(x)); return r;
}
__device__ __forceinline__ F2 frcp2(F2 a) {
    float lo, hi; upk(a, lo, hi); return pk(rcp_a(lo), rcp_a(hi));
}
__device__ __forceinline__ F2 frsq2(F2 a) {
    float lo, hi; upk(a, lo, hi); return pk(rsq_a(lo), rsq_a(hi));
}
__device__ __forceinline__ F2 fexp2(F2 a) {
    F2 t = fmul2(a, bc(1.4426950408889634f));   // 1 packed mul + 2 MUFU
    float lo, hi; upk(t, lo, hi);
    return pk(ex2_a(lo), ex2_a(hi));
}
#define EXPA(x) ex2_a(1.4426950408889634f * (x))

// ---------------- main kernel: 2 pixels per thread, packed across pixels ----------------
__global__ __launch_bounds__(32)
void pe_kernel(const float* __restrict__ X,     // (B,5,5)
               const float* __restrict__ Yg,    // (B,5)
               const float* __restrict__ ch0g,  // (B,1,3)
               const float* __restrict__ pf,    // (14,)
               const float* __restrict__ xag,   // (3,)
               const float* __restrict__ Sag,   // (3,3)
               const float* __restrict__ Seg,   // (5,5)
               const int*   __restrict__ nitp,
               float* __restrict__ out,         // (B,9)
               int B)
{
    int tIdx = blockIdx.x * blockDim.x + threadIdx.x;
    int pA = 2 * tIdx;
    if (pA >= B) return;
    int pB = min(pA + 1, B - 1);

    const float L[5] = {-0.275f, 0.025f, 0.5f, 0.70f, 1.15f};

    // ---- uniform (broadcast) parameters ----
    float p0=pf[0], p1=pf[1], p2=pf[2], p3=pf[3], p4=pf[4], p5=pf[5], p6=pf[6],
          p7=pf[7], p8=pf[8], p9=pf[9], p10=pf[10], p11=pf[11], p12=pf[12], p13=pf[13];

    float AphS[5], AcdS[5], BbsS[5];
    #pragma unroll
    for (int l = 0; l < 5; l++) {
        AphS[l] = p0 * 0.05f * (1.0f + p1 * 0.1f * L[l] + p2 * 0.01f);
        AcdS[l] = p5 * 0.1f * expf(-p6 * 1.7f * L[l]);
        BbsS[l] = p3 * 0.001f * (1.0f + p4 * 0.05f * L[l]);
    }
    const float cna = p12 * 0.005f;
    const float cnb = p13 * 0.005f;
    const float c7s = p7 * 0.089f;
    const float c8s = p8 * 0.1245f;

    // symmetrized matrices (uniform)
    float Se[5][5];
    #pragma unroll
    for (int i = 0; i < 5; i++)
        #pragma unroll
        for (int j = 0; j < 5; j++)
            Se[i][j] = 0.5f * (Seg[i*5 + j] + Seg[j*5 + i]);
    float SaS[3][3];
    #pragma unroll
    for (int i = 0; i < 3; i++)
        #pragma unroll
        for (int j = 0; j < 3; j++)
            SaS[i][j] = 0.5f * (Sag[i*3 + j] + Sag[j*3 + i]);
    float xa0 = xag[0], xa1 = xag[1], xa2 = xag[2];

    bool diag = (Se[0][1]==0.f && Se[0][2]==0.f && Se[0][3]==0.f && Se[0][4]==0.f &&
                 Se[1][2]==0.f && Se[1][3]==0.f && Se[1][4]==0.f &&
                 Se[2][3]==0.f && Se[2][4]==0.f && Se[3][4]==0.f &&
                 SaS[0][1]==0.f && SaS[0][2]==0.f && SaS[1][2]==0.f);

    // ---- per-pixel setup ----
    float feA[5], feB[5];
    #pragma unroll
    for (int l = 0; l < 5; l++) {
        float eA0 = X[pA*25 + l*5 + 0], eA1 = X[pA*25 + l*5 + 1];
        float eB0 = X[pB*25 + l*5 + 0], eB1 = X[pB*25 + l*5 + 1];
        feA[l] = __fdividef(eA0 + 0.5f*eA1, eA0 + eA1);
        feB[l] = __fdividef(eB0 + 0.5f*eB1, eB0 + eB1);
    }

    F2 ch[3], m[3], v[3];
    #pragma unroll
    for (int k = 0; k < 3; k++) {
        ch[k] = pk(ch0g[pA*3 + k], ch0g[pB*3 + k]);
        m[k] = bc(0.0f);
        v[k] = bc(1e-30f);   // exact-effect-free floor: keeps rsqrt finite
    }

    int iters = 50;
    if (nitp) {
        int it = *nitp;
        if (it >= 1 && it <= 100000000) iters = it;
        else {
            float f = __int_as_float(it);
            if (f >= 1.0f && f <= 1e8f) iters = (int)f;
        }
    }

    float b1t = 1.0f, b2t = 1.0f;

    if (diag) {
        // ===== lean fused diagonal path (fma-op-minimized) =====
        F2 ABSp[5], ABSn[5], ACDp[5], ACDn[5], BBSp[5], FE2[5], YFN[5];
        #pragma unroll
        for (int l = 0; l < 5; l++) {
            float ab = AphS[l] + BbsS[l];
            ABSp[l] = bc(ab);
            ABSn[l] = bc(-ab);
            ACDp[l] = bc(AcdS[l]);
            ACDn[l] = bc(-AcdS[l]);
            BBSp[l] = bc(BbsS[l]);
            FE2[l]  = pk(Se[l][l]*feA[l]*feA[l], Se[l][l]*feB[l]*feB[l]);
            YFN[l]  = pk(-__fdividef(Yg[pA*5 + l], feA[l]),
                         -__fdividef(Yg[pB*5 + l], feB[l]));
        }
        const F2 SAD[3] = { bc(SaS[0][0]), bc(SaS[1][1]), bc(SaS[2][2]) };
        const F2 BPD[3] = { bc(-SaS[0][0]*xa0), bc(-SaS[1][1]*xa1), bc(-SaS[2][2]*xa2) };
        const F2 CNAB  = bc(cna + cnb);
        const F2 CNBp  = bc(cnb);
        const F2 CNABn = bc(-(cna + cnb));
        const F2 C7p = bc(c7s), C8p = bc(c8s);
        const F2 C0057 = bc(0.0057f), C0012 = bc(0.0012f);
        const F2 CB1p = bc(ADAM_B1), C1MB1p = bc(1.0f - ADAM_B1);
        const F2 CB2p = bc(ADAM_B2), C1MB2p = bc(1.0f - ADAM_B2);

        for (int t = 0; t < iters; t++) {
            // scalar step size (off the packed critical path)
            b1t *= ADAM_B1; b2t *= ADAM_B2;
            float nlrt = -ADAM_LR * sqrt_a(1.0f - b2t) * rcp_a(1.0f - b1t);
            F2 NLRT2 = bc(nlrt);

            // direct packed exponentials (MUFU pipe)
            F2 chla = fexp2(ch[0]);
            F2 nap  = fexp2(ch[1]);
            F2 cdom = fexp2(ch[2]);

            F2 NC   = ffma2(CNAB, nap, C0057);   // (cna+cnb)*nap + .0045+.0012
            F2 DB1C = ffma2(CNBp, nap, C0012);   // cnb*nap + .0012

            // even/odd split accumulators: acc0, T (merged S0/S1), acc2
            F2 a0e = bc(0.0f), a0o = bc(0.0f);
            F2 Te  = bc(0.0f), To  = bc(0.0f);
            F2 a2e = bc(0.0f), a2o = bc(0.0f);

            #pragma unroll
            for (int l = 0; l < 5; l++) {
                F2 s  = ffma2(ABSp[l], chla, ffma2(ACDp[l], cdom, NC)); // a+bb
                F2 bb = ffma2(BBSp[l], chla, DB1C);
                F2 iv = frcp2(s);
                F2 u  = fmul2(bb, iv);
                F2 t1 = ffma2(C8p, u, C7p);
                F2 p  = ffma2(t1, u, YFN[l]);        // rrs/FE - Y/FE
                F2 d  = ffma2(C8p, u, t1);           // c7 + 2 c8 u
                F2 q  = fmul2(fmul2(FE2[l], iv), fmul2(p, d));
                F2 qu = fmul2(q, u);
                F2 tg = ffma2(u, ABSn[l], BBSp[l]);  // BBS - u*(Aph+Bbs)
                if (l & 1) {
                    a0o = ffma2(q, tg, a0o);
                    To  = ffma2(CNBp, q, To);
                    To  = ffma2(CNABn, qu, To);
                    a2o = ffma2(qu, ACDn[l], a2o);
                } else {
                    a0e = ffma2(q, tg, a0e);
                    Te  = ffma2(CNBp, q, Te);
                    Te  = ffma2(CNABn, qu, Te);
                    a2e = ffma2(qu, ACDn[l], a2e);
                }
            }
            F2 acc0 = fadd2(a0e, a0o);
            F2 T    = fadd2(Te, To);
            F2 acc2 = fadd2(a2e, a2o);

            // gradients
            F2 g0 = ffma2(acc0, chla, ffma2(SAD[0], ch[0], BPD[0]));
            F2 g1 = ffma2(T,    nap,  ffma2(SAD[1], ch[1], BPD[1]));
            F2 g2 = ffma2(acc2, cdom, ffma2(SAD[2], ch[2], BPD[2]));

            F2 g[3] = { g0, g1, g2 };
            #pragma unroll
            for (int k = 0; k < 3; k++) {
                m[k] = ffma2(g[k], C1MB1p, fmul2(m[k], CB1p));
                v[k] = ffma2(fmul2(g[k], g[k]), C1MB2p, fmul2(v[k], CB2p));
                F2 st = frsq2(v[k]);
                ch[k] = ffma2(fmul2(m[k], st), NLRT2, ch[k]);
            }
        }
    } else {
        // ===== general two-pass fallback (dense Se, Sa) — packed 2px =====
        const F2 CNA = bc(cna), CNBp = bc(cnb);
        const F2 C7p = bc(c7s), C8p = bc(c8s), C82 = bc(2.0f*c8s);
        const F2 C0045 = bc(0.0045f), C0012 = bc(0.0012f);
        const F2 NEG1 = bc(-1.0f), ONEg = bc(1.0f);
        const F2 CB1p = bc(ADAM_B1), C1MB1p = bc(1.0f - ADAM_B1);
        const F2 CB2p = bc(ADAM_B2), C1MB2p = bc(1.0f - ADAM_B2);
        const F2 APH[5] = { bc(AphS[0]), bc(AphS[1]), bc(AphS[2]), bc(AphS[3]), bc(AphS[4]) };
        const F2 ACD[5] = { bc(AcdS[0]), bc(AcdS[1]), bc(AcdS[2]), bc(AcdS[3]), bc(AcdS[4]) };
        const F2 BBS[5] = { bc(BbsS[0]), bc(BbsS[1]), bc(BbsS[2]), bc(BbsS[3]), bc(BbsS[4]) };
        F2 FE[5], Yp[5];
        #pragma unroll
        for (int l = 0; l < 5; l++) {
            FE[l] = pk(feA[l], feB[l]);
            Yp[l] = pk(-Yg[pA*5 + l], -Yg[pB*5 + l]);
        }
        float bp0 = -(SaS[0][0]*xa0 + SaS[0][1]*xa1 + SaS[0][2]*xa2);
        float bp1 = -(SaS[1][0]*xa0 + SaS[1][1]*xa1 + SaS[1][2]*xa2);
        float bp2 = -(SaS[2][0]*xa0 + SaS[2][1]*xa1 + SaS[2][2]*xa2);

        for (int t = 0; t < iters; t++) {
            F2 chla = fexp2(ch[0]);
            F2 nap  = fexp2(ch[1]);
            F2 cdom = fexp2(ch[2]);

            F2 da1  = fmul2(CNA, nap);
            F2 dbb1 = fmul2(CNBp, nap);

            F2 u[5], iv[5];
            float rA[5], rB[5];
            #pragma unroll
            for (int l = 0; l < 5; l++) {
                F2 da0  = fmul2(APH[l], chla);
                F2 da2  = fmul2(ACD[l], cdom);
                F2 dbb0 = fmul2(BBS[l], chla);
                F2 a  = fadd2(fadd2(da0, da2), fadd2(da1, C0045));
                F2 bb = fadd2(dbb0, fadd2(dbb1, C0012));
                F2 ivv = frcp2(fadd2(a, bb));
                F2 uv  = fmul2(bb, ivv);
                F2 rrs = fmul2(fmul2(ffma2(C8p, uv, C7p), uv), FE[l]);
                F2 rr  = fadd2(rrs, Yp[l]);
                upk(rr, rA[l], rB[l]);
                u[l] = uv; iv[l] = ivv;
            }

            float cA0, cB0, cA1, cB1, cA2, cB2;
            upk(ch[0], cA0, cB0); upk(ch[1], cA1, cB1); upk(ch[2], cA2, cB2);
            float gA0 = fmaf(SaS[0][0], cA0, fmaf(SaS[0][1], cA1, fmaf(SaS[0][2], cA2, bp0)));
            float gB0 = fmaf(SaS[0][0], cB0, fmaf(SaS[0][1], cB1, fmaf(SaS[0][2], cB2, bp0)));
            float gA1 = fmaf(SaS[1][0], cA0, fmaf(SaS[1][1], cA1, fmaf(SaS[1][2], cA2, bp1)));
            float gB1 = fmaf(SaS[1][0], cB0, fmaf(SaS[1][1], cB1, fmaf(SaS[1][2], cB2, bp1)));
            float gA2 = fmaf(SaS[2][0], cA0, fmaf(SaS[2][1], cA1, fmaf(SaS[2][2], cA2, bp2)));
            float gB2 = fmaf(SaS[2][0], cB0, fmaf(SaS[2][1], cB1, fmaf(SaS[2][2], cB2, bp2)));
            F2 g0 = pk(gA0, gB0);
            F2 g1 = pk(gA1, gB1);
            F2 g2 = pk(gA2, gB2);

            #pragma unroll
            for (int l = 0; l < 5; l++) {
                float wA = fmaf(Se[l][4], rA[4],
                           fmaf(Se[l][0], rA[0], Se[l][1]*rA[1]) +
                           fmaf(Se[l][2], rA[2], Se[l][3]*rA[3]));
                float wB = fmaf(Se[l][4], rB[4],
                           fmaf(Se[l][0], rB[0], Se[l][1]*rB[1]) +
                           fmaf(Se[l][2], rB[2], Se[l][3]*rB[3]));
                F2 w  = pk(wA, wB);
                F2 dg = fmul2(ffma2(C82, u[l], C7p), FE[l]);
                F2 q  = fmul2(fmul2(w, dg), iv[l]);

                F2 da0  = fmul2(APH[l], chla);
                F2 dbb0 = fmul2(BBS[l], chla);
                F2 da2  = fmul2(ACD[l], cdom);
                F2 om   = ffma2(u[l], NEG1, ONEg);

                F2 x0 = ffma2(fmul2(u[l], da0), NEG1, fmul2(om, dbb0));
                F2 x1 = ffma2(fmul2(u[l], da1), NEG1, fmul2(om, dbb1));
                F2 qun = fmul2(fmul2(q, u[l]), NEG1);
                g0 = ffma2(q, x0, g0);
                g1 = ffma2(q, x1, g1);
                g2 = ffma2(qun, da2, g2);
            }

            b1t *= ADAM_B1; b2t *= ADAM_B2;
            float nlrt = -ADAM_LR * sqrt_a(1.0f - b2t) * rcp_a(1.0f - b1t);
            F2 NLRT2 = bc(nlrt);
            F2 g[3] = { g0, g1, g2 };
            #pragma unroll
            for (int k = 0; k < 3; k++) {
                m[k] = ffma2(g[k], C1MB1p, fmul2(m[k], CB1p));
                v[k] = ffma2(fmul2(g[k], g[k]), C1MB2p, fmul2(v[k], CB2p));
                F2 st = frsq2(v[k]);
                ch[k] = ffma2(fmul2(m[k], st), NLRT2, ch[k]);
            }
        }
    }

    // ---- outputs: [ch0, kd(5), bbp(3)] per pixel ----
    float kfac = p9 * 0.9f + p10 * 0.1f;
    float chL[3], chH[3];
    #pragma unroll
    for (int k = 0; k < 3; k++) upk(ch[k], chL[k], chH[k]);

    #pragma unroll
    for (int s = 0; s < 2; s++) {
        int b = s ? pB : pA;
        const float* chp = s ? chH : chL;
        float chla = EXPA(chp[0]);
        float nap  = EXPA(chp[1]);
        float cdom = EXPA(chp[2]);

        out[b*9 + 0] = chp[0];
        #pragma unroll
        for (int l = 0; l < 5; l++) {
            float a  = 0.0045f + AphS[l]*chla + AcdS[l]*cdom + cna*nap;
            float bb = 0.0012f + BbsS[l]*chla + cnb*nap;
            float x3 = X[b*25 + l*5 + 3];
            float mu = 0.5f + 0.5f * rcp_a(1.0f + EXPA(-x3));
            out[b*9 + 1 + l] = (a + bb) * rcp_a(mu) * kfac;
        }
        const float L3[3] = {0.025f, 0.5f, 1.15f};
        #pragma unroll
        for (int j = 0; j < 3; j++) {
            out[b*9 + 6 + j] = p11 * (p3 * 0.001f * chla * (1.0f + p4 * 0.05f * L3[j]) + cnb * nap);
        }
    }
}

extern "C" void kernel_launch(void* const* d_in, const int* in_sizes, int n_in,
                              void* d_out, int out_size) {
    const float* X    = (const float*)d_in[0];
    const float* Y    = (const float*)d_in[1];
    const float* ch0  = (const float*)d_in[2];
    const float* pf   = (const float*)d_in[3];
    const float* xa   = (const float*)d_in[4];
    const float* Sa   = (const float*)d_in[5];
    const float* Se   = (const float*)d_in[6];
    const int*   nit  = (n_in >= 8) ? (const int*)d_in[7] : nullptr;
    float* out = (float*)d_out;

    int B = in_sizes[1] / 5;   // Y is (B,5)
    int nThreads = (B + 1) / 2;

    const int TPB = 32;
    int blocks = (nThreads + TPB - 1) / TPB;
    pe_kernel<<<blocks, TPB>>>(X, Y, ch0, pf, xa, Sa, Se, nit, out, B);
}